// round 14
// baseline (speedup 1.0000x reference)
#include <cuda_runtime.h>
#include <cuda_bf16.h>
#include <cstdint>

// ============================================================================
// Induction capsule routing, restructured (no e materialization):
//   c_i = (sum_s d_is x_is) @ W      (u_kernel; gemm NT)
//   b  += co * (x . (W c_raw))       (gemm TN; squash folded into fused b_update)
// Split-K(16) GEMM on mma.sync m16n8k16 bf16, 3-product bf16x2 split packed at
// staging. Block 128, CTA tile M64 x N32, k32 chunks, grid 1024 for occupancy.
// Iteration 0 specialized: uniform softmax, b stored (no zero kernel).
// ============================================================================

static constexpr int C_CAPS = 64;
static constexpr int S_LEN  = 128;
static constexpr int H_DIM  = 2048;
static constexpr int KSPLIT = 16;
static constexpr int KLEN   = H_DIM / KSPLIT;   // 128 -> 4 chunks of 32
static constexpr int NCHUNK = KLEN / 32;        // 4
static constexpr int BP     = 20;               // smem pitch (u32): 16 k-pairs + pad

// ---- scratch (device globals; allocation-free rule) ----
__device__ float g_b[C_CAPS * S_LEN];                       // logits
__device__ float g_u[C_CAPS * H_DIM];                       // weighted x sums
__device__ float g_part[KSPLIT][C_CAPS][H_DIM];             // split-K partials (8 MB)
__device__ float g_nrm2[C_CAPS][16];                        // per-block norm partials

// ============================================================================
// u_kernel<FIRST>: FIRST -> d uniform (b==0); else d = softmax(b[cap,:]).
// u[cap,h] = sum_s d[s] * x[cap,s,h].  grid (8, 64), block 256.
// ============================================================================
template <bool FIRST>
__global__ void __launch_bounds__(256) u_kernel(const float* __restrict__ x) {
    const int cap = blockIdx.y;
    const int tid = threadIdx.x;
    const int h = blockIdx.x * 256 + tid;
    __shared__ float d[S_LEN];

    if (!FIRST) {
        if (tid < S_LEN) d[tid] = g_b[cap * S_LEN + tid];
        __syncthreads();
        if (tid < 32) {
            float x0 = d[tid], x1 = d[tid + 32], x2 = d[tid + 64], x3 = d[tid + 96];
            float mx = fmaxf(fmaxf(x0, x1), fmaxf(x2, x3));
            #pragma unroll
            for (int o = 16; o > 0; o >>= 1) mx = fmaxf(mx, __shfl_xor_sync(0xffffffffu, mx, o));
            float e0 = __expf(x0 - mx), e1 = __expf(x1 - mx);
            float e2 = __expf(x2 - mx), e3 = __expf(x3 - mx);
            float s = (e0 + e1) + (e2 + e3);
            #pragma unroll
            for (int o = 16; o > 0; o >>= 1) s += __shfl_xor_sync(0xffffffffu, s, o);
            float inv = 1.0f / s;
            d[tid] = e0 * inv; d[tid + 32] = e1 * inv;
            d[tid + 64] = e2 * inv; d[tid + 96] = e3 * inv;
        }
        __syncthreads();
    }

    const float* xp = x + (size_t)cap * S_LEN * H_DIM + h;
    float a0 = 0.f, a1 = 0.f, a2 = 0.f, a3 = 0.f;
    if (FIRST) {
        #pragma unroll 8
        for (int s = 0; s < S_LEN; s += 4) {
            a0 += xp[(size_t)(s + 0) * H_DIM];
            a1 += xp[(size_t)(s + 1) * H_DIM];
            a2 += xp[(size_t)(s + 2) * H_DIM];
            a3 += xp[(size_t)(s + 3) * H_DIM];
        }
        g_u[cap * H_DIM + h] = ((a0 + a1) + (a2 + a3)) * (1.0f / S_LEN);
    } else {
        #pragma unroll 8
        for (int s = 0; s < S_LEN; s += 4) {
            a0 = fmaf(d[s + 0], xp[(size_t)(s + 0) * H_DIM], a0);
            a1 = fmaf(d[s + 1], xp[(size_t)(s + 1) * H_DIM], a1);
            a2 = fmaf(d[s + 2], xp[(size_t)(s + 2) * H_DIM], a2);
            a3 = fmaf(d[s + 3], xp[(size_t)(s + 3) * H_DIM], a3);
        }
        g_u[cap * H_DIM + h] = (a0 + a1) + (a2 + a3);
    }
}

// ============================================================================
// bf16 split/pack helpers
// ============================================================================
static __device__ __forceinline__ void pack_split(float e, float o,
                                                  uint32_t& hi, uint32_t& lo) {
    __nv_bfloat162 h = __floats2bfloat162_rn(e, o);           // x=e(k even), y=o(k odd)
    float re = e - __bfloat162float(h.x);
    float ro = o - __bfloat162float(h.y);
    __nv_bfloat162 l = __floats2bfloat162_rn(re, ro);
    hi = *(uint32_t*)&h;
    lo = *(uint32_t*)&l;
}
static __device__ __forceinline__ void mma_bf16(float* c, const uint32_t* a,
                                                uint32_t b0, uint32_t b1) {
    asm("mma.sync.aligned.m16n8k16.row.col.f32.bf16.bf16.f32 "
        "{%0,%1,%2,%3}, {%4,%5,%6,%7}, {%8,%9}, {%0,%1,%2,%3};"
        : "+f"(c[0]), "+f"(c[1]), "+f"(c[2]), "+f"(c[3])
        : "r"(a[0]), "r"(a[1]), "r"(a[2]), "r"(a[3]), "r"(b0), "r"(b1));
}

// ============================================================================
// gemm_mma<BK_CONTIG>: g_part[kz][m][j] = sum_{k in chunk kz} A[m][k]*Bval(k,j)
//   BK_CONTIG=true  (TN): Bval(k,j) = B[(j0+j)*H + k]      (v = c @ W^T)
//   BK_CONTIG=false (NT): Bval(k,j) = B[k*H + (j0+j)]      (c = u @ W)
//   grid (64, 16) = 1024 CTAs, block 128 (4 warps). CTA tile M=64 x N=32,
//   K=128 in 4 chunks of 32 (double-buffered, 1 barrier per chunk).
//   Smem: packed bf16x2 hi/lo, pitch 20 (conflict-free fragment LDS).
// ============================================================================
template <bool BK_CONTIG>
__global__ void __launch_bounds__(128) gemm_mma_kernel(const float* __restrict__ A,
                                                       const float* __restrict__ B) {
    __shared__ uint32_t Ahi[2][64][BP], Alo[2][64][BP];
    __shared__ uint32_t Bhi[2][32][BP], Blo[2][32][BP];

    const int tid = threadIdx.x;
    const int lane = tid & 31;
    const int w = tid >> 5;
    const int j0 = blockIdx.x * 32;
    const int kz = blockIdx.y;
    const int k0 = kz * KLEN;

    // ---- A staging: 4 slots/thread (64 rows x 8 f4-kgroups = 512 slots) ----
    int am[4], ak[4];
    const float* ap[4];
    #pragma unroll
    for (int i = 0; i < 4; i++) {
        const int s = tid + 128 * i;
        am[i] = s >> 3; ak[i] = (s & 7) * 4;
        ap[i] = A + (size_t)am[i] * H_DIM + k0 + ak[i];
    }
    // ---- B staging: 2 slots/thread ----
    // TN: 32 j-rows x 8 k-groups = 256 slots.  NT: 16 k-pairs x 16 j-pairs.
    int bjr[2], bkg[2], kp[2], jq[2];
    const float* tp[2];
    const float* np[2];
    #pragma unroll
    for (int i = 0; i < 2; i++) {
        const int s = tid + 128 * i;
        bjr[i] = s >> 3; bkg[i] = (s & 7) * 4;
        tp[i] = B + (size_t)(j0 + bjr[i]) * H_DIM + k0 + bkg[i];
        kp[i] = s >> 4; jq[i] = s & 15;
        np[i] = B + (size_t)(k0 + 2 * kp[i]) * H_DIM + j0 + 2 * jq[i];
    }

    // prologue: chunk 0 global loads
    float4 ar[4], tb[2];
    float2 nb0[2], nb1[2];
    #pragma unroll
    for (int i = 0; i < 4; i++) ar[i] = *(const float4*)ap[i];
    #pragma unroll
    for (int i = 0; i < 2; i++) {
        if (BK_CONTIG) {
            tb[i] = *(const float4*)tp[i];
        } else {
            nb0[i] = *(const float2*)np[i];
            nb1[i] = *(const float2*)(np[i] + H_DIM);
        }
    }

    const int g = lane >> 2, t = lane & 3;
    const int mrow = w * 16 + g;

    float acc[4][4] = {};

    for (int kc = 0; kc < NCHUNK; kc++) {
        const int cur = kc & 1;
        // ---- stage A (split+pack k-pairs) ----
        #pragma unroll
        for (int i = 0; i < 4; i++) {
            uint32_t h, l;
            const int kq = ak[i] / 2;
            pack_split(ar[i].x, ar[i].y, h, l);
            Ahi[cur][am[i]][kq] = h;     Alo[cur][am[i]][kq] = l;
            pack_split(ar[i].z, ar[i].w, h, l);
            Ahi[cur][am[i]][kq + 1] = h; Alo[cur][am[i]][kq + 1] = l;
        }
        // ---- stage B ----
        #pragma unroll
        for (int i = 0; i < 2; i++) {
            uint32_t h, l;
            if (BK_CONTIG) {
                const int kq = bkg[i] / 2;
                pack_split(tb[i].x, tb[i].y, h, l);
                Bhi[cur][bjr[i]][kq] = h;     Blo[cur][bjr[i]][kq] = l;
                pack_split(tb[i].z, tb[i].w, h, l);
                Bhi[cur][bjr[i]][kq + 1] = h; Blo[cur][bjr[i]][kq + 1] = l;
            } else {
                pack_split(nb0[i].x, nb1[i].x, h, l);     // j = 2*jq
                Bhi[cur][2 * jq[i]][kp[i]] = h;     Blo[cur][2 * jq[i]][kp[i]] = l;
                pack_split(nb0[i].y, nb1[i].y, h, l);     // j = 2*jq+1
                Bhi[cur][2 * jq[i] + 1][kp[i]] = h; Blo[cur][2 * jq[i] + 1][kp[i]] = l;
            }
        }
        __syncthreads();

        // ---- prefetch next chunk ----
        if (kc + 1 < NCHUNK) {
            const int ko = (kc + 1) * 32;
            #pragma unroll
            for (int i = 0; i < 4; i++) ar[i] = *(const float4*)(ap[i] + ko);
            #pragma unroll
            for (int i = 0; i < 2; i++) {
                if (BK_CONTIG) {
                    tb[i] = *(const float4*)(tp[i] + ko);
                } else {
                    const size_t ro = (size_t)ko * H_DIM;
                    nb0[i] = *(const float2*)(np[i] + ro);
                    nb1[i] = *(const float2*)(np[i] + ro + H_DIM);
                }
            }
        }

        // ---- two k16 halves: fragments + mma, no split ops ----
        #pragma unroll
        for (int half = 0; half < 2; half++) {
            const int o2 = half * 8;                   // k-pair offset
            uint32_t ah[4], al[4];
            ah[0] = Ahi[cur][mrow    ][o2 + t];     al[0] = Alo[cur][mrow    ][o2 + t];
            ah[1] = Ahi[cur][mrow + 8][o2 + t];     al[1] = Alo[cur][mrow + 8][o2 + t];
            ah[2] = Ahi[cur][mrow    ][o2 + t + 4]; al[2] = Alo[cur][mrow    ][o2 + t + 4];
            ah[3] = Ahi[cur][mrow + 8][o2 + t + 4]; al[3] = Alo[cur][mrow + 8][o2 + t + 4];
            #pragma unroll
            for (int nt = 0; nt < 4; nt++) {
                const int bn = nt * 8 + g;
                uint32_t bh0 = Bhi[cur][bn][o2 + t], bh1 = Bhi[cur][bn][o2 + t + 4];
                uint32_t bl0 = Blo[cur][bn][o2 + t], bl1 = Blo[cur][bn][o2 + t + 4];
                mma_bf16(acc[nt], ah, bh0, bh1);   // hi*hi
                mma_bf16(acc[nt], ah, bl0, bl1);   // hi*lo
                mma_bf16(acc[nt], al, bh0, bh1);   // lo*hi
            }
        }
        // single barrier per chunk: stores for chunk kc+2 (same buffer) happen
        // only after barrier kc+1, which all warps reach after reading chunk kc.
    }

    // epilogue: c0=(g,2t) c1=(g,2t+1) c2=(g+8,2t) c3=(g+8,2t+1) per n-tile
    #pragma unroll
    for (int nt = 0; nt < 4; nt++) {
        const int col = j0 + nt * 8 + 2 * t;
        *(float2*)&g_part[kz][mrow    ][col] = make_float2(acc[nt][0], acc[nt][1]);
        *(float2*)&g_part[kz][mrow + 8][col] = make_float2(acc[nt][2], acc[nt][3]);
    }
}

// ============================================================================
// z-split reduce (16 planes): lane = (zq<<3)|jj; each lane sums 4 planes, then
// 2 shfl rounds (fixed order, deterministic).
// ============================================================================
static __device__ __forceinline__ float4 zsplit_sum(int cap, int j, int zq) {
    float4 a = make_float4(0.f, 0.f, 0.f, 0.f);
    #pragma unroll
    for (int i = 0; i < 4; i++) {
        float4 p = *(const float4*)&g_part[zq * 4 + i][cap][j];
        a.x += p.x; a.y += p.y; a.z += p.z; a.w += p.w;
    }
    #pragma unroll
    for (int o = 8; o <= 16; o <<= 1) {
        a.x += __shfl_xor_sync(0xffffffffu, a.x, o);
        a.y += __shfl_xor_sync(0xffffffffu, a.y, o);
        a.z += __shfl_xor_sync(0xffffffffu, a.z, o);
        a.w += __shfl_xor_sync(0xffffffffu, a.w, o);
    }
    return a;
}

// ============================================================================
// reduce_c_norm: out[cap][:] = sum_z g_part[z][cap][:] (RAW c); g_nrm2 partials.
//   grid (16, 64) = 1024 CTAs, block 128.
// ============================================================================
__global__ void __launch_bounds__(128) reduce_c_norm_kernel(float* __restrict__ out) {
    const int cap = blockIdx.y;
    const int jb = blockIdx.x;
    const int tid = threadIdx.x;
    const int w = tid >> 5, lane = tid & 31;
    const int jj = lane & 7, zq = lane >> 3;
    const int j = (jb * 32 + w * 8 + jj) * 4;

    float4 a = zsplit_sum(cap, j, zq);
    if (zq == 0) *(float4*)(out + cap * H_DIM + j) = a;

    float sq = a.x * a.x + a.y * a.y + a.z * a.z + a.w * a.w;
    #pragma unroll
    for (int o = 1; o <= 4; o <<= 1) sq += __shfl_xor_sync(0xffffffffu, sq, o);
    __shared__ float ws[4];
    if (lane == 0) ws[w] = sq;
    __syncthreads();
    if (tid == 0) g_nrm2[cap][jb] = (ws[0] + ws[1]) + (ws[2] + ws[3]);
}

// ============================================================================
// squash_scale (final iteration only): coeff from 16 norm partials; scale out.
// ============================================================================
__global__ void __launch_bounds__(256) squash_scale_kernel(float* __restrict__ out) {
    const int cap = blockIdx.x;
    const int tid = threadIdx.x;
    __shared__ float coeff_s;
    if (tid == 0) {
        float s = 0.f;
        #pragma unroll
        for (int k = 0; k < 16; k++) s += g_nrm2[cap][k];
        coeff_s = s / (1.0f + s) / sqrtf(s + 1e-9f);
    }
    __syncthreads();
    const float co = coeff_s;
    float* row = out + cap * H_DIM;
    #pragma unroll
    for (int r = 0; r < 2; r++) {
        int j = (tid + 256 * r) * 4;
        float4 v = *(float4*)(row + j);
        *(float4*)(row + j) = make_float4(v.x * co, v.y * co, v.z * co, v.w * co);
    }
}

// ============================================================================
// b_update<FIRST> (fused): coeff from g_nrm2; v = co * sum_z part[z][cap][:]
// -> smem; b[cap,s] (=|+=) x[cap,s,:] . v.  grid (4, 64), block 1024; warp/s.
// ============================================================================
template <bool FIRST>
__global__ void __launch_bounds__(1024) b_update_kernel(const float* __restrict__ x) {
    const int cap = blockIdx.y;
    const int sb = blockIdx.x;
    const int tid = threadIdx.x;
    __shared__ float vs[H_DIM];
    __shared__ float coeff_s;

    if (tid == 0) {
        float s = 0.f;
        #pragma unroll
        for (int k = 0; k < 16; k++) s += g_nrm2[cap][k];
        coeff_s = s / (1.0f + s) / sqrtf(s + 1e-9f);
    }
    __syncthreads();
    const float co = coeff_s;

    if (tid < 512) {
        const int j = tid * 4;
        float4 a = make_float4(0.f, 0.f, 0.f, 0.f);
        #pragma unroll
        for (int z = 0; z < KSPLIT; z++) {
            float4 p = *(const float4*)&g_part[z][cap][j];
            a.x += p.x; a.y += p.y; a.z += p.z; a.w += p.w;
        }
        *(float4*)(vs + j) = make_float4(a.x * co, a.y * co, a.z * co, a.w * co);
    }
    __syncthreads();

    const int warp = tid >> 5, lane = tid & 31;
    const int s = sb * 32 + warp;
    const float4* xp = (const float4*)(x + ((size_t)cap * S_LEN + s) * H_DIM);
    const float4* vp = (const float4*)vs;
    float acc = 0.f;
    #pragma unroll 4
    for (int j = lane; j < H_DIM / 4; j += 32) {
        float4 ev = xp[j], cv = vp[j];
        acc = fmaf(ev.x, cv.x, acc);
        acc = fmaf(ev.y, cv.y, acc);
        acc = fmaf(ev.z, cv.z, acc);
        acc = fmaf(ev.w, cv.w, acc);
    }
    #pragma unroll
    for (int o = 16; o > 0; o >>= 1) acc += __shfl_xor_sync(0xffffffffu, acc, o);
    if (lane == 0) {
        if (FIRST) g_b[cap * S_LEN + s] = acc;
        else       g_b[cap * S_LEN + s] += acc;
    }
}

// ============================================================================
// kernel_launch
// ============================================================================
extern "C" void kernel_launch(void* const* d_in, const int* in_sizes, int n_in,
                              void* d_out, int out_size) {
    const float* x = (const float*)d_in[0];   // [64,128,2048] fp32
    const float* W = (const float*)d_in[1];   // [2048,2048] fp32
    float* out = (float*)d_out;               // [64,2048] fp32 — holds c

    float* u_ptr;
    cudaGetSymbolAddress((void**)&u_ptr, g_u);

    const dim3 gemm_grid(H_DIM / 32, KSPLIT);
    const dim3 ugrid(H_DIM / 256, C_CAPS);
    const dim3 rgrid(16, C_CAPS);
    const dim3 bgrid(4, C_CAPS);

    // iteration 0 (b == 0: uniform softmax; b stored, not accumulated)
    u_kernel<true><<<ugrid, 256>>>(x);
    gemm_mma_kernel<false><<<gemm_grid, 128>>>(u_ptr, W);
    reduce_c_norm_kernel<<<rgrid, 128>>>(out);
    gemm_mma_kernel<true><<<gemm_grid, 128>>>(out, W);
    b_update_kernel<true><<<bgrid, 1024>>>(x);

    // iteration 1
    u_kernel<false><<<ugrid, 256>>>(x);
    gemm_mma_kernel<false><<<gemm_grid, 128>>>(u_ptr, W);
    reduce_c_norm_kernel<<<rgrid, 128>>>(out);
    gemm_mma_kernel<true><<<gemm_grid, 128>>>(out, W);
    b_update_kernel<false><<<bgrid, 1024>>>(x);

    // iteration 2 (final: squash the output)
    u_kernel<false><<<ugrid, 256>>>(x);
    gemm_mma_kernel<false><<<gemm_grid, 128>>>(u_ptr, W);
    reduce_c_norm_kernel<<<rgrid, 128>>>(out);
    squash_scale_kernel<<<C_CAPS, 256>>>(out);
}

// round 15
// speedup vs baseline: 1.1387x; 1.1387x over previous
#include <cuda_runtime.h>
#include <cuda_bf16.h>
#include <cstdint>

// ============================================================================
// Induction capsule routing, restructured (no e materialization):
//   c_i = (sum_s d_is x_is) @ W      (u_kernel; gemm NT)
//   b  += co * (x . (W c_raw))       (gemm TN; squash folded into fused b_update)
// Split-K(16) GEMM on mma.sync m16n8k16 bf16, 3-product bf16x2 split packed at
// staging into {hi,lo} uint2 smem -> all fragment loads are LDS.64.
// A: M-major pitch 20 (uint2). B: K-major pitch 68 (uint2). Both conflict-free.
// ============================================================================

static constexpr int C_CAPS = 64;
static constexpr int S_LEN  = 128;
static constexpr int H_DIM  = 2048;
static constexpr int KSPLIT = 16;
static constexpr int KLEN   = H_DIM / KSPLIT;   // 128 -> 4 chunks of 32
static constexpr int NCHUNK = KLEN / 32;        // 4
static constexpr int PA     = 20;               // A pitch (uint2): mod16=4 -> CF frags
static constexpr int PB     = 68;               // B pitch (uint2): mod16=4 -> CF frags

// ---- scratch (device globals; allocation-free rule) ----
__device__ float g_b[C_CAPS * S_LEN];                       // logits
__device__ float g_u[C_CAPS * H_DIM];                       // weighted x sums
__device__ float g_part[KSPLIT][C_CAPS][H_DIM];             // split-K partials (8 MB)
__device__ float g_nrm2[C_CAPS][16];                        // per-block norm partials

// ============================================================================
// u_kernel<FIRST>: FIRST -> d uniform (b==0); else d = softmax(b[cap,:]).
// u[cap,h] = sum_s d[s] * x[cap,s,h].  grid (8, 64), block 256.
// ============================================================================
template <bool FIRST>
__global__ void __launch_bounds__(256) u_kernel(const float* __restrict__ x) {
    const int cap = blockIdx.y;
    const int tid = threadIdx.x;
    const int h = blockIdx.x * 256 + tid;
    __shared__ float d[S_LEN];

    if (!FIRST) {
        if (tid < S_LEN) d[tid] = g_b[cap * S_LEN + tid];
        __syncthreads();
        if (tid < 32) {
            float x0 = d[tid], x1 = d[tid + 32], x2 = d[tid + 64], x3 = d[tid + 96];
            float mx = fmaxf(fmaxf(x0, x1), fmaxf(x2, x3));
            #pragma unroll
            for (int o = 16; o > 0; o >>= 1) mx = fmaxf(mx, __shfl_xor_sync(0xffffffffu, mx, o));
            float e0 = __expf(x0 - mx), e1 = __expf(x1 - mx);
            float e2 = __expf(x2 - mx), e3 = __expf(x3 - mx);
            float s = (e0 + e1) + (e2 + e3);
            #pragma unroll
            for (int o = 16; o > 0; o >>= 1) s += __shfl_xor_sync(0xffffffffu, s, o);
            float inv = 1.0f / s;
            d[tid] = e0 * inv; d[tid + 32] = e1 * inv;
            d[tid + 64] = e2 * inv; d[tid + 96] = e3 * inv;
        }
        __syncthreads();
    }

    const float* xp = x + (size_t)cap * S_LEN * H_DIM + h;
    float a0 = 0.f, a1 = 0.f, a2 = 0.f, a3 = 0.f;
    if (FIRST) {
        #pragma unroll 8
        for (int s = 0; s < S_LEN; s += 4) {
            a0 += xp[(size_t)(s + 0) * H_DIM];
            a1 += xp[(size_t)(s + 1) * H_DIM];
            a2 += xp[(size_t)(s + 2) * H_DIM];
            a3 += xp[(size_t)(s + 3) * H_DIM];
        }
        g_u[cap * H_DIM + h] = ((a0 + a1) + (a2 + a3)) * (1.0f / S_LEN);
    } else {
        #pragma unroll 8
        for (int s = 0; s < S_LEN; s += 4) {
            a0 = fmaf(d[s + 0], xp[(size_t)(s + 0) * H_DIM], a0);
            a1 = fmaf(d[s + 1], xp[(size_t)(s + 1) * H_DIM], a1);
            a2 = fmaf(d[s + 2], xp[(size_t)(s + 2) * H_DIM], a2);
            a3 = fmaf(d[s + 3], xp[(size_t)(s + 3) * H_DIM], a3);
        }
        g_u[cap * H_DIM + h] = (a0 + a1) + (a2 + a3);
    }
}

// ============================================================================
// bf16 split/pack helpers
// ============================================================================
static __device__ __forceinline__ void pack_split(float e, float o,
                                                  uint32_t& hi, uint32_t& lo) {
    __nv_bfloat162 h = __floats2bfloat162_rn(e, o);           // x=e(k even), y=o(k odd)
    float re = e - __bfloat162float(h.x);
    float ro = o - __bfloat162float(h.y);
    __nv_bfloat162 l = __floats2bfloat162_rn(re, ro);
    hi = *(uint32_t*)&h;
    lo = *(uint32_t*)&l;
}
static __device__ __forceinline__ void mma_bf16(float* c, const uint32_t* a,
                                                uint32_t b0, uint32_t b1) {
    asm("mma.sync.aligned.m16n8k16.row.col.f32.bf16.bf16.f32 "
        "{%0,%1,%2,%3}, {%4,%5,%6,%7}, {%8,%9}, {%0,%1,%2,%3};"
        : "+f"(c[0]), "+f"(c[1]), "+f"(c[2]), "+f"(c[3])
        : "r"(a[0]), "r"(a[1]), "r"(a[2]), "r"(a[3]), "r"(b0), "r"(b1));
}

// ============================================================================
// gemm_mma<BK_CONTIG>: g_part[kz][m][j] = sum_{k in chunk kz} A[m][k]*Bval(k,j)
//   BK_CONTIG=true  (TN): Bval(k,j) = B[(j0+j)*H + k]      (v = c @ W^T)
//   BK_CONTIG=false (NT): Bval(k,j) = B[k*H + (j0+j)]      (c = u @ W)
//   grid (32, 16) = 512 CTAs, block 128 (4 warps). CTA tile M=64 x N=64,
//   K=128 in 4 chunks of 32 (double-buffered, 1 barrier per chunk).
//   Smem: A uint2[64][20] M-major; B uint2[16][68] K-major (kpair rows).
//   Inner loop: 20 LDS.64 + 24 HMMA per k16 half — zero split ops.
// ============================================================================
template <bool BK_CONTIG>
__global__ void __launch_bounds__(128) gemm_mma_kernel(const float* __restrict__ A,
                                                       const float* __restrict__ B) {
    __shared__ uint2 Aa[2][64][PA];
    __shared__ uint2 Bb[2][16][PB];

    const int tid = threadIdx.x;
    const int lane = tid & 31;
    const int w = tid >> 5;
    const int j0 = blockIdx.x * 64;
    const int kz = blockIdx.y;
    const int k0 = kz * KLEN;

    // ---- A staging: 4 slots/thread (64 rows x 8 f4-kgroups = 512 slots) ----
    int am[4], akq[4];
    const float* ap[4];
    #pragma unroll
    for (int i = 0; i < 4; i++) {
        const int s = tid + 128 * i;
        am[i] = s >> 3; akq[i] = (s & 7) * 2;      // k-pair index (even)
        ap[i] = A + (size_t)am[i] * H_DIM + k0 + akq[i] * 2;
    }
    // ---- B staging: 4 slots/thread ----
    // TN: 64 j-rows x 8 k-groups = 512 slots.  NT: 16 kpairs x 32 j-pairs.
    int bjr[4], bkq[4], kp[4], jq[4];
    const float* tp[4];
    const float* np[4];
    #pragma unroll
    for (int i = 0; i < 4; i++) {
        const int s = tid + 128 * i;
        bjr[i] = s >> 3; bkq[i] = (s & 7) * 2;
        tp[i] = B + (size_t)(j0 + bjr[i]) * H_DIM + k0 + bkq[i] * 2;
        kp[i] = s >> 5; jq[i] = s & 31;
        np[i] = B + (size_t)(k0 + 2 * kp[i]) * H_DIM + j0 + 2 * jq[i];
    }

    // prologue: chunk 0 global loads
    float4 ar[4], tb[4];
    float2 nb0[4], nb1[4];
    #pragma unroll
    for (int i = 0; i < 4; i++) {
        ar[i] = *(const float4*)ap[i];
        if (BK_CONTIG) {
            tb[i] = *(const float4*)tp[i];
        } else {
            nb0[i] = *(const float2*)np[i];
            nb1[i] = *(const float2*)(np[i] + H_DIM);
        }
    }

    const int g = lane >> 2, t = lane & 3;
    const int mrow = w * 16 + g;

    float acc[8][4] = {};

    for (int kc = 0; kc < NCHUNK; kc++) {
        const int cur = kc & 1;
        // ---- stage A: one STS.128 {h0,l0,h1,l1} per slot (conflict-free) ----
        #pragma unroll
        for (int i = 0; i < 4; i++) {
            uint32_t h0, l0, h1, l1;
            pack_split(ar[i].x, ar[i].y, h0, l0);
            pack_split(ar[i].z, ar[i].w, h1, l1);
            *(uint4*)&Aa[cur][am[i]][akq[i]] = make_uint4(h0, l0, h1, l1);
        }
        // ---- stage B (K-major) ----
        #pragma unroll
        for (int i = 0; i < 4; i++) {
            uint32_t h0, l0, h1, l1;
            if (BK_CONTIG) {
                // j row, 2 k-pairs -> 2 STS.64 to rows bkq, bkq+1 (col bjr)
                pack_split(tb[i].x, tb[i].y, h0, l0);
                pack_split(tb[i].z, tb[i].w, h1, l1);
                Bb[cur][bkq[i]    ][bjr[i]] = make_uint2(h0, l0);
                Bb[cur][bkq[i] + 1][bjr[i]] = make_uint2(h1, l1);
            } else {
                // one k-pair, 2 adjacent j -> one STS.128 at [kp][2jq]
                pack_split(nb0[i].x, nb1[i].x, h0, l0);   // j = 2*jq
                pack_split(nb0[i].y, nb1[i].y, h1, l1);   // j = 2*jq+1
                *(uint4*)&Bb[cur][kp[i]][2 * jq[i]] = make_uint4(h0, l0, h1, l1);
            }
        }
        __syncthreads();

        // ---- prefetch next chunk ----
        if (kc + 1 < NCHUNK) {
            const int ko = (kc + 1) * 32;
            #pragma unroll
            for (int i = 0; i < 4; i++) {
                ar[i] = *(const float4*)(ap[i] + ko);
                if (BK_CONTIG) {
                    tb[i] = *(const float4*)(tp[i] + ko);
                } else {
                    const size_t ro = (size_t)ko * H_DIM;
                    nb0[i] = *(const float2*)(np[i] + ro);
                    nb1[i] = *(const float2*)(np[i] + ro + H_DIM);
                }
            }
        }

        // ---- two k16 halves: LDS.64 fragments + mma ----
        #pragma unroll
        for (int half = 0; half < 2; half++) {
            const int o2 = half * 8;                   // k-pair offset
            const uint2 a0 = Aa[cur][mrow    ][o2 + t];
            const uint2 a1 = Aa[cur][mrow + 8][o2 + t];
            const uint2 a2 = Aa[cur][mrow    ][o2 + t + 4];
            const uint2 a3 = Aa[cur][mrow + 8][o2 + t + 4];
            const uint32_t ah[4] = {a0.x, a1.x, a2.x, a3.x};
            const uint32_t al[4] = {a0.y, a1.y, a2.y, a3.y};
            #pragma unroll
            for (int nt = 0; nt < 8; nt++) {
                const int bn = nt * 8 + g;
                const uint2 b0 = Bb[cur][o2 + t    ][bn];
                const uint2 b1 = Bb[cur][o2 + t + 4][bn];
                mma_bf16(acc[nt], ah, b0.x, b1.x);   // hi*hi
                mma_bf16(acc[nt], ah, b0.y, b1.y);   // hi*lo
                mma_bf16(acc[nt], al, b0.x, b1.x);   // lo*hi
            }
        }
        // single barrier per chunk: stores for chunk kc+2 (same buffer) happen
        // only after barrier kc+1, which all warps reach after reading chunk kc.
    }

    // epilogue: c0=(g,2t) c1=(g,2t+1) c2=(g+8,2t) c3=(g+8,2t+1) per n-tile
    #pragma unroll
    for (int nt = 0; nt < 8; nt++) {
        const int col = j0 + nt * 8 + 2 * t;
        *(float2*)&g_part[kz][mrow    ][col] = make_float2(acc[nt][0], acc[nt][1]);
        *(float2*)&g_part[kz][mrow + 8][col] = make_float2(acc[nt][2], acc[nt][3]);
    }
}

// ============================================================================
// z-split reduce (16 planes): lane = (zq<<3)|jj; each lane sums 4 planes, then
// 2 shfl rounds (fixed order, deterministic).
// ============================================================================
static __device__ __forceinline__ float4 zsplit_sum(int cap, int j, int zq) {
    float4 a = make_float4(0.f, 0.f, 0.f, 0.f);
    #pragma unroll
    for (int i = 0; i < 4; i++) {
        float4 p = *(const float4*)&g_part[zq * 4 + i][cap][j];
        a.x += p.x; a.y += p.y; a.z += p.z; a.w += p.w;
    }
    #pragma unroll
    for (int o = 8; o <= 16; o <<= 1) {
        a.x += __shfl_xor_sync(0xffffffffu, a.x, o);
        a.y += __shfl_xor_sync(0xffffffffu, a.y, o);
        a.z += __shfl_xor_sync(0xffffffffu, a.z, o);
        a.w += __shfl_xor_sync(0xffffffffu, a.w, o);
    }
    return a;
}

// ============================================================================
// reduce_c_norm: out[cap][:] = sum_z g_part[z][cap][:] (RAW c); g_nrm2 partials.
//   grid (16, 64) = 1024 CTAs, block 128.
// ============================================================================
__global__ void __launch_bounds__(128) reduce_c_norm_kernel(float* __restrict__ out) {
    const int cap = blockIdx.y;
    const int jb = blockIdx.x;
    const int tid = threadIdx.x;
    const int w = tid >> 5, lane = tid & 31;
    const int jj = lane & 7, zq = lane >> 3;
    const int j = (jb * 32 + w * 8 + jj) * 4;

    float4 a = zsplit_sum(cap, j, zq);
    if (zq == 0) *(float4*)(out + cap * H_DIM + j) = a;

    float sq = a.x * a.x + a.y * a.y + a.z * a.z + a.w * a.w;
    #pragma unroll
    for (int o = 1; o <= 4; o <<= 1) sq += __shfl_xor_sync(0xffffffffu, sq, o);
    __shared__ float ws[4];
    if (lane == 0) ws[w] = sq;
    __syncthreads();
    if (tid == 0) g_nrm2[cap][jb] = (ws[0] + ws[1]) + (ws[2] + ws[3]);
}

// ============================================================================
// squash_scale (final iteration only): coeff from 16 norm partials; scale out.
// ============================================================================
__global__ void __launch_bounds__(256) squash_scale_kernel(float* __restrict__ out) {
    const int cap = blockIdx.x;
    const int tid = threadIdx.x;
    __shared__ float coeff_s;
    if (tid == 0) {
        float s = 0.f;
        #pragma unroll
        for (int k = 0; k < 16; k++) s += g_nrm2[cap][k];
        coeff_s = s / (1.0f + s) / sqrtf(s + 1e-9f);
    }
    __syncthreads();
    const float co = coeff_s;
    float* row = out + cap * H_DIM;
    #pragma unroll
    for (int r = 0; r < 2; r++) {
        int j = (tid + 256 * r) * 4;
        float4 v = *(float4*)(row + j);
        *(float4*)(row + j) = make_float4(v.x * co, v.y * co, v.z * co, v.w * co);
    }
}

// ============================================================================
// b_update<FIRST> (fused): coeff from g_nrm2; v = co * sum_z part[z][cap][:]
// -> smem; b[cap,s] (=|+=) x[cap,s,:] . v.  grid (4, 64), block 1024; warp/s.
// ============================================================================
template <bool FIRST>
__global__ void __launch_bounds__(1024) b_update_kernel(const float* __restrict__ x) {
    const int cap = blockIdx.y;
    const int sb = blockIdx.x;
    const int tid = threadIdx.x;
    __shared__ float vs[H_DIM];
    __shared__ float coeff_s;

    if (tid == 0) {
        float s = 0.f;
        #pragma unroll
        for (int k = 0; k < 16; k++) s += g_nrm2[cap][k];
        coeff_s = s / (1.0f + s) / sqrtf(s + 1e-9f);
    }
    __syncthreads();
    const float co = coeff_s;

    if (tid < 512) {
        const int j = tid * 4;
        float4 a = make_float4(0.f, 0.f, 0.f, 0.f);
        #pragma unroll
        for (int z = 0; z < KSPLIT; z++) {
            float4 p = *(const float4*)&g_part[z][cap][j];
            a.x += p.x; a.y += p.y; a.z += p.z; a.w += p.w;
        }
        *(float4*)(vs + j) = make_float4(a.x * co, a.y * co, a.z * co, a.w * co);
    }
    __syncthreads();

    const int warp = tid >> 5, lane = tid & 31;
    const int s = sb * 32 + warp;
    const float4* xp = (const float4*)(x + ((size_t)cap * S_LEN + s) * H_DIM);
    const float4* vp = (const float4*)vs;
    float acc = 0.f;
    #pragma unroll 4
    for (int j = lane; j < H_DIM / 4; j += 32) {
        float4 ev = xp[j], cv = vp[j];
        acc = fmaf(ev.x, cv.x, acc);
        acc = fmaf(ev.y, cv.y, acc);
        acc = fmaf(ev.z, cv.z, acc);
        acc = fmaf(ev.w, cv.w, acc);
    }
    #pragma unroll
    for (int o = 16; o > 0; o >>= 1) acc += __shfl_xor_sync(0xffffffffu, acc, o);
    if (lane == 0) {
        if (FIRST) g_b[cap * S_LEN + s] = acc;
        else       g_b[cap * S_LEN + s] += acc;
    }
}

// ============================================================================
// kernel_launch
// ============================================================================
extern "C" void kernel_launch(void* const* d_in, const int* in_sizes, int n_in,
                              void* d_out, int out_size) {
    const float* x = (const float*)d_in[0];   // [64,128,2048] fp32
    const float* W = (const float*)d_in[1];   // [2048,2048] fp32
    float* out = (float*)d_out;               // [64,2048] fp32 — holds c

    float* u_ptr;
    cudaGetSymbolAddress((void**)&u_ptr, g_u);

    const dim3 gemm_grid(H_DIM / 64, KSPLIT);
    const dim3 ugrid(H_DIM / 256, C_CAPS);
    const dim3 rgrid(16, C_CAPS);
    const dim3 bgrid(4, C_CAPS);

    // iteration 0 (b == 0: uniform softmax; b stored, not accumulated)
    u_kernel<true><<<ugrid, 256>>>(x);
    gemm_mma_kernel<false><<<gemm_grid, 128>>>(u_ptr, W);
    reduce_c_norm_kernel<<<rgrid, 128>>>(out);
    gemm_mma_kernel<true><<<gemm_grid, 128>>>(out, W);
    b_update_kernel<true><<<bgrid, 1024>>>(x);

    // iteration 1
    u_kernel<false><<<ugrid, 256>>>(x);
    gemm_mma_kernel<false><<<gemm_grid, 128>>>(u_ptr, W);
    reduce_c_norm_kernel<<<rgrid, 128>>>(out);
    gemm_mma_kernel<true><<<gemm_grid, 128>>>(out, W);
    b_update_kernel<false><<<bgrid, 1024>>>(x);

    // iteration 2 (final: squash the output)
    u_kernel<false><<<ugrid, 256>>>(x);
    gemm_mma_kernel<false><<<gemm_grid, 128>>>(u_ptr, W);
    reduce_c_norm_kernel<<<rgrid, 128>>>(out);
    squash_scale_kernel<<<C_CAPS, 256>>>(out);
}